// round 15
// baseline (speedup 1.0000x reference)
#include <cuda_runtime.h>
#include <cuda_fp16.h>
#include <cstdint>

// ---------------------------------------------------------------------------
// ShapletLearner via single-pass fp16 mma.sync m16n8k16.
// R15 = R14 + batch amortization: 512 CTAs x 4 batch rows each (one resident
// wave). shp/B-frags/ssq/fc_w loaded once; ts prefetched for b+1 via
// cp.async during b's main loop (DRAM latency hidden). Per-b prologue is the
// R14 L1-light pack/scan path. Main loop unchanged (R11/R14 pipeline).
// ---------------------------------------------------------------------------

constexpr int Bc = 2048;
constexpr int Qc = 1024;
constexpr int Kc = 32;
constexpr int Lc = 64;
constexpr int Sc = Qc - Kc + 1;   // 993
constexpr int RS = 164;           // wsq_T row stride (== 4 mod 32: 8 banks)
constexpr int BPC = 4;            // batch rows per CTA
constexpr int NCTA = Bc / BPC;    // 512

// D = A*B + {c0,c0,c1,c1}
#define MMAC(d0,d1,d2,d3, a0,a1,a2,a3, b0,b1, c0,c1) \
    asm("mma.sync.aligned.m16n8k16.row.col.f32.f16.f16.f32 " \
        "{%0,%1,%2,%3}, {%4,%5,%6,%7}, {%8,%9}, {%10,%11,%12,%13};" \
        : "=f"(d0), "=f"(d1), "=f"(d2), "=f"(d3) \
        : "r"(a0), "r"(a1), "r"(a2), "r"(a3), "r"(b0), "r"(b1), \
          "f"(c0), "f"(c0), "f"(c1), "f"(c1))

// D += A*B
#define MMAB(d0,d1,d2,d3, a0,a1,a2,a3, b0,b1) \
    asm("mma.sync.aligned.m16n8k16.row.col.f32.f16.f16.f32 " \
        "{%0,%1,%2,%3}, {%4,%5,%6,%7}, {%8,%9}, {%0,%1,%2,%3};" \
        : "+f"(d0), "+f"(d1), "+f"(d2), "+f"(d3) \
        : "r"(a0), "r"(a1), "r"(a2), "r"(a3), "r"(b0), "r"(b1))

#define TILE_MMA(O, S, TT) do { \
    enum { I0 = (O) % 6, I1 = ((O) + 1) % 6, I2 = ((O) + 2) % 6, \
           I3 = ((O) + 3) % 6, I4 = ((O) + 4) % 6, S5 = ((O) + 5) % 6 }; \
    const int s0_ = (TT) << 4; \
    MMAC(d##S##0,d##S##1,d##S##2,d##S##3, rr[I0],rr[I1],rr[I1],rr[I2], \
         Bf[0][0][0],Bf[0][0][1], wq##S.x, wq##S.y); \
    MMAC(d##S##4,d##S##5,d##S##6,d##S##7, rr[I0],rr[I1],rr[I1],rr[I2], \
         Bf[1][0][0],Bf[1][0][1], wq##S.x, wq##S.y); \
    MMAB(d##S##0,d##S##1,d##S##2,d##S##3, rr[I2],rr[I3],rr[I3],rr[I4], \
         Bf[0][1][0],Bf[0][1][1]); \
    MMAB(d##S##4,d##S##5,d##S##6,d##S##7, rr[I2],rr[I3],rr[I3],rr[I4], \
         Bf[1][1][0],Bf[1][1][1]); \
    wq##S = *reinterpret_cast<const float2*>(wsq_T + nrowRS + 2 * (TT) + 4); \
    { const int gi_ = s0_ + tbx; \
      rr[S5] = pair16[gi_ + 40]; \
      rr[I0] = pair16[gi_ + 48]; } \
} while (0)

#define MERGE_S(S) do { \
    mn00 = fminf(mn00, d##S##0);  mn01 = fminf(mn01, d##S##1); \
    mn02 = fminf(mn02, d##S##2);  mn03 = fminf(mn03, d##S##3); \
    mn10 = fminf(mn10, d##S##4);  mn11 = fminf(mn11, d##S##5); \
    mn12 = fminf(mn12, d##S##6);  mn13 = fminf(mn13, d##S##7); \
} while (0)

static __device__ __forceinline__ uint32_t pack_f16x2(float lo, float hi) {
    uint32_t r;
    asm("cvt.rn.f16x2.f32 %0, %1, %2;" : "=r"(r) : "f"(hi), "f"(lo));
    return r;
}
static __device__ __forceinline__ uint32_t smem_u32(const void* p) {
    uint32_t a;
    asm("{ .reg .u64 t; cvta.to.shared.u64 t, %1; cvt.u32.u64 %0, t; }"
        : "=r"(a) : "l"(p));
    return a;
}
static __device__ __forceinline__ void cp_async16(uint32_t dst, const void* src) {
    asm volatile("cp.async.cg.shared.global [%0], [%1], 16;"
                 :: "r"(dst), "l"(src) : "memory");
}

__global__ __launch_bounds__(128) void shapelet_hmma(
    const float* __restrict__ ts,        // [B, Q]
    const float* __restrict__ shp,       // [L, K]
    const float* __restrict__ fc_w,      // [2, L]
    const float* __restrict__ fc_b,      // [2]
    float* __restrict__ out)             // [B, 2]
{
    __shared__ __align__(16) float    ts_db[2][1152];  // ping-pong ts buffers
    __shared__ __align__(16) uint32_t pair16[1120];
    __shared__ __align__(16) float    wsq_T[8 * RS];
    __shared__ __align__(16) float    shp_sh[Lc * 33];
    __shared__ float nh[4 * 32];
    __shared__ float warp_tot[4];
    __shared__ float ssq_sh[Lc];
    __shared__ float dsh[Lc];

    const int tid  = threadIdx.x;
    const int w    = tid >> 5;
    const int lane = tid & 31;
    const int nrow = lane >> 2;
    const int kq   = lane & 3;
    const int b0   = blockIdx.x * BPC;

    // ---- one-time: zero pads of both ts buffers ----
    if (tid < 32) {
        #pragma unroll
        for (int q = 0; q < 2; q++) {
            float4* dz = reinterpret_cast<float4*>(ts_db[q]);
            dz[256 + tid] = make_float4(0.f, 0.f, 0.f, 0.f);
        }
    }

    // ---- one-time: prefetch ts[b0] into buffer 0 (cp.async) ----
    {
        const uint32_t dst = smem_u32(ts_db[0]) + tid * 16u;
        const float* src = ts + (size_t)b0 * Qc + tid * 4;
        cp_async16(dst, src);
        cp_async16(dst + 2048u, src + 512);
        asm volatile("cp.async.commit_group;" ::: "memory");
    }

    // ---- one-time: stage shp (coalesced, padded) ----
    {
        const float4* gs4 = reinterpret_cast<const float4*>(shp);
        #pragma unroll
        for (int j = 0; j < 4; j++) {
            const int i4 = tid + 128 * j;
            const float4 v = gs4[i4];
            const int base = i4 * 4;
            float* d = &shp_sh[(base >> 5) * 33 + (base & 31)];
            d[0] = v.x; d[1] = v.y; d[2] = v.z; d[3] = v.w;
        }
    }

    // ---- one-time: fc_w preload (warps 0,1) ----
    float wv0 = 0.f, wv1 = 0.f, bias = 0.f;
    if (tid < 64) {
        const int c = tid >> 5, l = tid & 31;
        wv0 = fc_w[c * Lc + l];
        wv1 = fc_w[c * Lc + l + 32];
        bias = fc_b[c];
    }
    __syncthreads();   // shp_sh ready

    // ---- one-time: ssq + B fragments from shp_sh ----
    if (tid < Lc) {
        float s = 0.f;
        #pragma unroll
        for (int k = 0; k < Kc; k++) {
            const float v = shp_sh[tid * 33 + k];
            s = fmaf(v, v, s);
        }
        ssq_sh[tid] = s;
    }
    uint32_t Bf[2][2][2];
    #pragma unroll
    for (int nt = 0; nt < 2; nt++)
        #pragma unroll
        for (int kc = 0; kc < 2; kc++)
            #pragma unroll
            for (int j = 0; j < 2; j++) {
                const int n = w * 16 + nt * 8 + nrow;
                const int k = 16 * kc + 8 * j + 2 * kq;
                Bf[nt][kc][j] = pack_f16x2(-2.0f * shp_sh[n * 33 + k],
                                           -2.0f * shp_sh[n * 33 + k + 1]);
            }

    const int tbx = nrow + 2 * kq;
    const int nrowRS = nrow * RS;

    // ================= batch-row loop =================
    #pragma unroll 1
    for (int it = 0; it < BPC; it++) {
        const int buf = it & 1;
        const float* tsb = ts_db[buf];

        asm volatile("cp.async.wait_group 0;" ::: "memory");
        __syncthreads();   // ts[b] ready; previous main loop / FC done

        // ---- per-b: packed fp16 pair array ----
        #pragma unroll
        for (int i = tid; i < 1120; i += 128)
            pair16[i] = pack_f16x2(tsb[i], tsb[i + 1]);

        // ---- per-b: register scan for P(s) ----
        float ex[8], e = 0.f, warp_excl;
        {
            const float4 q0 = reinterpret_cast<const float4*>(tsb)[tid * 2];
            const float4 q1 = reinterpret_cast<const float4*>(tsb)[tid * 2 + 1];
            const float sq[8] = { q0.x*q0.x, q0.y*q0.y, q0.z*q0.z, q0.w*q0.w,
                                  q1.x*q1.x, q1.y*q1.y, q1.z*q1.z, q1.w*q1.w };
            #pragma unroll
            for (int k = 0; k < 8; k++) { ex[k] = e; e += sq[k]; }
            float v = e;
            #pragma unroll
            for (int off = 1; off < 32; off <<= 1) {
                const float n = __shfl_up_sync(0xffffffffu, v, off);
                if (lane >= off) v += n;
            }
            if (lane == 31) warp_tot[w] = v;
            warp_excl = v - e;
        }
        __syncthreads();   // warp_tot ready

        float pk[8], total = 0.f;
        {
            float wb = 0.f;
            #pragma unroll
            for (int j = 0; j < 4; j++) {
                total += warp_tot[j];
                if (j < w) wb += warp_tot[j];
            }
            const float tb0 = wb + warp_excl;
            #pragma unroll
            for (int k = 0; k < 8; k++) pk[k] = tb0 + ex[k];
            if (lane < 4) {
                #pragma unroll
                for (int k = 0; k < 8; k++) nh[w * 32 + lane * 8 + k] = pk[k];
            }
        }
        __syncthreads();   // nh ready

        // ---- per-b: wsq_T = P(s+32) - P(s), transposed ----
        {
            float p4[8];
            #pragma unroll
            for (int k = 0; k < 8; k++)
                p4[k] = __shfl_down_sync(0xffffffffu, pk[k], 4);
            if (lane >= 28 && w < 3) {
                #pragma unroll
                for (int k = 0; k < 8; k++)
                    p4[k] = nh[(w + 1) * 32 + (lane - 28) * 8 + k];
            }
            #pragma unroll
            for (int k = 0; k < 8; k++) {
                const int s = tid * 8 + k;
                float wv = 1e38f;
                if (s < Sc) wv = (s == 992) ? (total - pk[k]) : (p4[k] - pk[k]);
                wsq_T[k * RS + tid] = wv;
            }
            if (tid < 64) {
                const int s = 1024 + tid;
                wsq_T[(s & 7) * RS + (s >> 3)] = 1e38f;
            }
        }
        __syncthreads();   // pair16 + wsq_T ready

        // ---- prefetch next b's ts into the other buffer ----
        if (it + 1 < BPC) {
            const uint32_t dst = smem_u32(ts_db[buf ^ 1]) + tid * 16u;
            const float* src = ts + (size_t)(b0 + it + 1) * Qc + tid * 4;
            cp_async16(dst, src);
            cp_async16(dst + 2048u, src + 512);
            asm volatile("cp.async.commit_group;" ::: "memory");
        }

        // ---- main loop: 66 m16 tiles ----
        float mn00 = 3.4e38f, mn01 = 3.4e38f, mn02 = 3.4e38f, mn03 = 3.4e38f;
        float mn10 = 3.4e38f, mn11 = 3.4e38f, mn12 = 3.4e38f, mn13 = 3.4e38f;

        uint32_t rr[6];
        #pragma unroll
        for (int m = 0; m < 5; m++) rr[m] = pair16[tbx + 8 * m];
        rr[5] = 0u;

        float dA0,dA1,dA2,dA3,dA4,dA5,dA6,dA7;
        float dB0,dB1,dB2,dB3,dB4,dB5,dB6,dB7;

        float2 wqA = *reinterpret_cast<const float2*>(wsq_T + nrowRS);
        float2 wqB = *reinterpret_cast<const float2*>(wsq_T + nrowRS + 2);

        #pragma unroll 1
        for (int q = 0; q < 11; q++) {
            const int t6 = q * 6;
            TILE_MMA(0, A, t6);
            TILE_MMA(2, B, t6 + 1);
            MERGE_S(A);
            TILE_MMA(4, A, t6 + 2);
            MERGE_S(B);
            TILE_MMA(0, B, t6 + 3);
            MERGE_S(A);
            TILE_MMA(2, A, t6 + 4);
            MERGE_S(B);
            TILE_MMA(4, B, t6 + 5);
            MERGE_S(A);
            MERGE_S(B);
        }

        // ---- per-b reduction ----
        float m0 = fminf(mn00, mn02);
        float m1 = fminf(mn01, mn03);
        float m2 = fminf(mn10, mn12);
        float m3 = fminf(mn11, mn13);
        #pragma unroll
        for (int off = 4; off < 32; off <<= 1) {
            m0 = fminf(m0, __shfl_xor_sync(0xffffffffu, m0, off));
            m1 = fminf(m1, __shfl_xor_sync(0xffffffffu, m1, off));
            m2 = fminf(m2, __shfl_xor_sync(0xffffffffu, m2, off));
            m3 = fminf(m3, __shfl_xor_sync(0xffffffffu, m3, off));
        }
        if (nrow == 0) {
            const int n0 = w * 16 + 2 * kq;
            dsh[n0]     = (m0 + ssq_sh[n0])     * (1.0f / Kc);
            dsh[n0 + 1] = (m1 + ssq_sh[n0 + 1]) * (1.0f / Kc);
            dsh[n0 + 8] = (m2 + ssq_sh[n0 + 8]) * (1.0f / Kc);
            dsh[n0 + 9] = (m3 + ssq_sh[n0 + 9]) * (1.0f / Kc);
        }
        __syncthreads();

        // ---- per-b FC epilogue (fc_w in registers) ----
        if (tid < 64) {
            const int c = tid >> 5;
            const int l = tid & 31;
            float p = dsh[l] * wv0 + dsh[l + 32] * wv1;
            #pragma unroll
            for (int off = 16; off > 0; off >>= 1)
                p += __shfl_down_sync(0xffffffffu, p, off);
            if (l == 0) out[(b0 + it) * 2 + c] = p + bias;
        }
    }
}

extern "C" void kernel_launch(void* const* d_in, const int* in_sizes, int n_in,
                              void* d_out, int out_size)
{
    (void)in_sizes; (void)n_in; (void)out_size;
    const float* ts   = (const float*)d_in[0];
    const float* shp  = (const float*)d_in[1];
    const float* fc_w = (const float*)d_in[2];
    const float* fc_b = (const float*)d_in[3];
    float* out        = (float*)d_out;
    shapelet_hmma<<<NCTA, 128>>>(ts, shp, fc_w, fc_b, out);
}

// round 16
// speedup vs baseline: 1.1481x; 1.1481x over previous
#include <cuda_runtime.h>
#include <cuda_fp16.h>
#include <cstdint>

// ---------------------------------------------------------------------------
// ShapletLearner via single-pass fp16 mma.sync m16n8k16.
// R16 = R15 with BPC=2 (1024 CTAs): all CTAs co-resident in ONE wave
// (residency limit ~7 CTAs/SM at 72 regs / 28KB smem), restoring R14's
// occupancy while keeping 2x head amortization + cp.async ts prefetch.
// ---------------------------------------------------------------------------

constexpr int Bc = 2048;
constexpr int Qc = 1024;
constexpr int Kc = 32;
constexpr int Lc = 64;
constexpr int Sc = Qc - Kc + 1;   // 993
constexpr int RS = 164;           // wsq_T row stride (== 4 mod 32: 8 banks)
constexpr int BPC = 2;            // batch rows per CTA
constexpr int NCTA = Bc / BPC;    // 1024

// D = A*B + {c0,c0,c1,c1}
#define MMAC(d0,d1,d2,d3, a0,a1,a2,a3, b0,b1, c0,c1) \
    asm("mma.sync.aligned.m16n8k16.row.col.f32.f16.f16.f32 " \
        "{%0,%1,%2,%3}, {%4,%5,%6,%7}, {%8,%9}, {%10,%11,%12,%13};" \
        : "=f"(d0), "=f"(d1), "=f"(d2), "=f"(d3) \
        : "r"(a0), "r"(a1), "r"(a2), "r"(a3), "r"(b0), "r"(b1), \
          "f"(c0), "f"(c0), "f"(c1), "f"(c1))

// D += A*B
#define MMAB(d0,d1,d2,d3, a0,a1,a2,a3, b0,b1) \
    asm("mma.sync.aligned.m16n8k16.row.col.f32.f16.f16.f32 " \
        "{%0,%1,%2,%3}, {%4,%5,%6,%7}, {%8,%9}, {%0,%1,%2,%3};" \
        : "+f"(d0), "+f"(d1), "+f"(d2), "+f"(d3) \
        : "r"(a0), "r"(a1), "r"(a2), "r"(a3), "r"(b0), "r"(b1))

#define TILE_MMA(O, S, TT) do { \
    enum { I0 = (O) % 6, I1 = ((O) + 1) % 6, I2 = ((O) + 2) % 6, \
           I3 = ((O) + 3) % 6, I4 = ((O) + 4) % 6, S5 = ((O) + 5) % 6 }; \
    const int s0_ = (TT) << 4; \
    MMAC(d##S##0,d##S##1,d##S##2,d##S##3, rr[I0],rr[I1],rr[I1],rr[I2], \
         Bf[0][0][0],Bf[0][0][1], wq##S.x, wq##S.y); \
    MMAC(d##S##4,d##S##5,d##S##6,d##S##7, rr[I0],rr[I1],rr[I1],rr[I2], \
         Bf[1][0][0],Bf[1][0][1], wq##S.x, wq##S.y); \
    MMAB(d##S##0,d##S##1,d##S##2,d##S##3, rr[I2],rr[I3],rr[I3],rr[I4], \
         Bf[0][1][0],Bf[0][1][1]); \
    MMAB(d##S##4,d##S##5,d##S##6,d##S##7, rr[I2],rr[I3],rr[I3],rr[I4], \
         Bf[1][1][0],Bf[1][1][1]); \
    wq##S = *reinterpret_cast<const float2*>(wsq_T + nrowRS + 2 * (TT) + 4); \
    { const int gi_ = s0_ + tbx; \
      rr[S5] = pair16[gi_ + 40]; \
      rr[I0] = pair16[gi_ + 48]; } \
} while (0)

#define MERGE_S(S) do { \
    mn00 = fminf(mn00, d##S##0);  mn01 = fminf(mn01, d##S##1); \
    mn02 = fminf(mn02, d##S##2);  mn03 = fminf(mn03, d##S##3); \
    mn10 = fminf(mn10, d##S##4);  mn11 = fminf(mn11, d##S##5); \
    mn12 = fminf(mn12, d##S##6);  mn13 = fminf(mn13, d##S##7); \
} while (0)

static __device__ __forceinline__ uint32_t pack_f16x2(float lo, float hi) {
    uint32_t r;
    asm("cvt.rn.f16x2.f32 %0, %1, %2;" : "=r"(r) : "f"(hi), "f"(lo));
    return r;
}
static __device__ __forceinline__ uint32_t smem_u32(const void* p) {
    uint32_t a;
    asm("{ .reg .u64 t; cvta.to.shared.u64 t, %1; cvt.u32.u64 %0, t; }"
        : "=r"(a) : "l"(p));
    return a;
}
static __device__ __forceinline__ void cp_async16(uint32_t dst, const void* src) {
    asm volatile("cp.async.cg.shared.global [%0], [%1], 16;"
                 :: "r"(dst), "l"(src) : "memory");
}

__global__ __launch_bounds__(128) void shapelet_hmma(
    const float* __restrict__ ts,        // [B, Q]
    const float* __restrict__ shp,       // [L, K]
    const float* __restrict__ fc_w,      // [2, L]
    const float* __restrict__ fc_b,      // [2]
    float* __restrict__ out)             // [B, 2]
{
    __shared__ __align__(16) float    ts_db[2][1152];  // ping-pong ts buffers
    __shared__ __align__(16) uint32_t pair16[1120];
    __shared__ __align__(16) float    wsq_T[8 * RS];
    __shared__ __align__(16) float    shp_sh[Lc * 33];
    __shared__ float nh[4 * 32];
    __shared__ float warp_tot[4];
    __shared__ float ssq_sh[Lc];
    __shared__ float dsh[Lc];

    const int tid  = threadIdx.x;
    const int w    = tid >> 5;
    const int lane = tid & 31;
    const int nrow = lane >> 2;
    const int kq   = lane & 3;
    const int b0   = blockIdx.x * BPC;

    // ---- one-time: zero pads of both ts buffers ----
    if (tid < 32) {
        #pragma unroll
        for (int q = 0; q < 2; q++) {
            float4* dz = reinterpret_cast<float4*>(ts_db[q]);
            dz[256 + tid] = make_float4(0.f, 0.f, 0.f, 0.f);
        }
    }

    // ---- one-time: prefetch ts[b0] into buffer 0 (cp.async) ----
    {
        const uint32_t dst = smem_u32(ts_db[0]) + tid * 16u;
        const float* src = ts + (size_t)b0 * Qc + tid * 4;
        cp_async16(dst, src);
        cp_async16(dst + 2048u, src + 512);
        asm volatile("cp.async.commit_group;" ::: "memory");
    }

    // ---- one-time: stage shp (coalesced, padded) ----
    {
        const float4* gs4 = reinterpret_cast<const float4*>(shp);
        #pragma unroll
        for (int j = 0; j < 4; j++) {
            const int i4 = tid + 128 * j;
            const float4 v = gs4[i4];
            const int base = i4 * 4;
            float* d = &shp_sh[(base >> 5) * 33 + (base & 31)];
            d[0] = v.x; d[1] = v.y; d[2] = v.z; d[3] = v.w;
        }
    }

    // ---- one-time: fc_w preload (warps 0,1) ----
    float wv0 = 0.f, wv1 = 0.f, bias = 0.f;
    if (tid < 64) {
        const int c = tid >> 5, l = tid & 31;
        wv0 = fc_w[c * Lc + l];
        wv1 = fc_w[c * Lc + l + 32];
        bias = fc_b[c];
    }
    __syncthreads();   // shp_sh ready

    // ---- one-time: ssq + B fragments from shp_sh ----
    if (tid < Lc) {
        float s = 0.f;
        #pragma unroll
        for (int k = 0; k < Kc; k++) {
            const float v = shp_sh[tid * 33 + k];
            s = fmaf(v, v, s);
        }
        ssq_sh[tid] = s;
    }
    uint32_t Bf[2][2][2];
    #pragma unroll
    for (int nt = 0; nt < 2; nt++)
        #pragma unroll
        for (int kc = 0; kc < 2; kc++)
            #pragma unroll
            for (int j = 0; j < 2; j++) {
                const int n = w * 16 + nt * 8 + nrow;
                const int k = 16 * kc + 8 * j + 2 * kq;
                Bf[nt][kc][j] = pack_f16x2(-2.0f * shp_sh[n * 33 + k],
                                           -2.0f * shp_sh[n * 33 + k + 1]);
            }

    const int tbx = nrow + 2 * kq;
    const int nrowRS = nrow * RS;

    // ================= batch-row loop =================
    #pragma unroll 1
    for (int it = 0; it < BPC; it++) {
        const int buf = it & 1;
        const float* tsb = ts_db[buf];

        asm volatile("cp.async.wait_group 0;" ::: "memory");
        __syncthreads();   // ts[b] ready; previous main loop / FC done

        // ---- per-b: packed fp16 pair array ----
        #pragma unroll
        for (int i = tid; i < 1120; i += 128)
            pair16[i] = pack_f16x2(tsb[i], tsb[i + 1]);

        // ---- per-b: register scan for P(s) ----
        float ex[8], e = 0.f, warp_excl;
        {
            const float4 q0 = reinterpret_cast<const float4*>(tsb)[tid * 2];
            const float4 q1 = reinterpret_cast<const float4*>(tsb)[tid * 2 + 1];
            const float sq[8] = { q0.x*q0.x, q0.y*q0.y, q0.z*q0.z, q0.w*q0.w,
                                  q1.x*q1.x, q1.y*q1.y, q1.z*q1.z, q1.w*q1.w };
            #pragma unroll
            for (int k = 0; k < 8; k++) { ex[k] = e; e += sq[k]; }
            float v = e;
            #pragma unroll
            for (int off = 1; off < 32; off <<= 1) {
                const float n = __shfl_up_sync(0xffffffffu, v, off);
                if (lane >= off) v += n;
            }
            if (lane == 31) warp_tot[w] = v;
            warp_excl = v - e;
        }
        __syncthreads();   // warp_tot ready

        float pk[8], total = 0.f;
        {
            float wb = 0.f;
            #pragma unroll
            for (int j = 0; j < 4; j++) {
                total += warp_tot[j];
                if (j < w) wb += warp_tot[j];
            }
            const float tb0 = wb + warp_excl;
            #pragma unroll
            for (int k = 0; k < 8; k++) pk[k] = tb0 + ex[k];
            if (lane < 4) {
                #pragma unroll
                for (int k = 0; k < 8; k++) nh[w * 32 + lane * 8 + k] = pk[k];
            }
        }
        __syncthreads();   // nh ready

        // ---- per-b: wsq_T = P(s+32) - P(s), transposed ----
        {
            float p4[8];
            #pragma unroll
            for (int k = 0; k < 8; k++)
                p4[k] = __shfl_down_sync(0xffffffffu, pk[k], 4);
            if (lane >= 28 && w < 3) {
                #pragma unroll
                for (int k = 0; k < 8; k++)
                    p4[k] = nh[(w + 1) * 32 + (lane - 28) * 8 + k];
            }
            #pragma unroll
            for (int k = 0; k < 8; k++) {
                const int s = tid * 8 + k;
                float wv = 1e38f;
                if (s < Sc) wv = (s == 992) ? (total - pk[k]) : (p4[k] - pk[k]);
                wsq_T[k * RS + tid] = wv;
            }
            if (tid < 64) {
                const int s = 1024 + tid;
                wsq_T[(s & 7) * RS + (s >> 3)] = 1e38f;
            }
        }
        __syncthreads();   // pair16 + wsq_T ready

        // ---- prefetch next b's ts into the other buffer ----
        if (it + 1 < BPC) {
            const uint32_t dst = smem_u32(ts_db[buf ^ 1]) + tid * 16u;
            const float* src = ts + (size_t)(b0 + it + 1) * Qc + tid * 4;
            cp_async16(dst, src);
            cp_async16(dst + 2048u, src + 512);
            asm volatile("cp.async.commit_group;" ::: "memory");
        }

        // ---- main loop: 66 m16 tiles ----
        float mn00 = 3.4e38f, mn01 = 3.4e38f, mn02 = 3.4e38f, mn03 = 3.4e38f;
        float mn10 = 3.4e38f, mn11 = 3.4e38f, mn12 = 3.4e38f, mn13 = 3.4e38f;

        uint32_t rr[6];
        #pragma unroll
        for (int m = 0; m < 5; m++) rr[m] = pair16[tbx + 8 * m];
        rr[5] = 0u;

        float dA0,dA1,dA2,dA3,dA4,dA5,dA6,dA7;
        float dB0,dB1,dB2,dB3,dB4,dB5,dB6,dB7;

        float2 wqA = *reinterpret_cast<const float2*>(wsq_T + nrowRS);
        float2 wqB = *reinterpret_cast<const float2*>(wsq_T + nrowRS + 2);

        #pragma unroll 1
        for (int q = 0; q < 11; q++) {
            const int t6 = q * 6;
            TILE_MMA(0, A, t6);
            TILE_MMA(2, B, t6 + 1);
            MERGE_S(A);
            TILE_MMA(4, A, t6 + 2);
            MERGE_S(B);
            TILE_MMA(0, B, t6 + 3);
            MERGE_S(A);
            TILE_MMA(2, A, t6 + 4);
            MERGE_S(B);
            TILE_MMA(4, B, t6 + 5);
            MERGE_S(A);
            MERGE_S(B);
        }

        // ---- per-b reduction ----
        float m0 = fminf(mn00, mn02);
        float m1 = fminf(mn01, mn03);
        float m2 = fminf(mn10, mn12);
        float m3 = fminf(mn11, mn13);
        #pragma unroll
        for (int off = 4; off < 32; off <<= 1) {
            m0 = fminf(m0, __shfl_xor_sync(0xffffffffu, m0, off));
            m1 = fminf(m1, __shfl_xor_sync(0xffffffffu, m1, off));
            m2 = fminf(m2, __shfl_xor_sync(0xffffffffu, m2, off));
            m3 = fminf(m3, __shfl_xor_sync(0xffffffffu, m3, off));
        }
        if (nrow == 0) {
            const int n0 = w * 16 + 2 * kq;
            dsh[n0]     = (m0 + ssq_sh[n0])     * (1.0f / Kc);
            dsh[n0 + 1] = (m1 + ssq_sh[n0 + 1]) * (1.0f / Kc);
            dsh[n0 + 8] = (m2 + ssq_sh[n0 + 8]) * (1.0f / Kc);
            dsh[n0 + 9] = (m3 + ssq_sh[n0 + 9]) * (1.0f / Kc);
        }
        __syncthreads();

        // ---- per-b FC epilogue (fc_w in registers) ----
        if (tid < 64) {
            const int c = tid >> 5;
            const int l = tid & 31;
            float p = dsh[l] * wv0 + dsh[l + 32] * wv1;
            #pragma unroll
            for (int off = 16; off > 0; off >>= 1)
                p += __shfl_down_sync(0xffffffffu, p, off);
            if (l == 0) out[(b0 + it) * 2 + c] = p + bias;
        }
    }
}

extern "C" void kernel_launch(void* const* d_in, const int* in_sizes, int n_in,
                              void* d_out, int out_size)
{
    (void)in_sizes; (void)n_in; (void)out_size;
    const float* ts   = (const float*)d_in[0];
    const float* shp  = (const float*)d_in[1];
    const float* fc_w = (const float*)d_in[2];
    const float* fc_b = (const float*)d_in[3];
    float* out        = (float*)d_out;
    shapelet_hmma<<<NCTA, 128>>>(ts, shp, fc_w, fc_b, out);
}

// round 17
// speedup vs baseline: 1.1492x; 1.0010x over previous
#include <cuda_runtime.h>
#include <cuda_fp16.h>
#include <cstdint>

// ---------------------------------------------------------------------------
// ShapletLearner via single-pass fp16 mma.sync m16n8k16.
// R17 = R14 + issue-slot diet + occupancy bump:
//   - ring refill via packed uint2 pp[i]={pair(i),pair(i+8)} -> 1 LDS.64/tile
//   - wq via one LDS.128 per B-tile covering the next TWO tiles
//   - __launch_bounds__(128,8): 8 CTAs/SM (regs<=64, smem ~27KB, RS=140)
//   - everything else identical to R14 (scan prologue, pipelined merge)
// ---------------------------------------------------------------------------

constexpr int Bc = 2048;
constexpr int Qc = 1024;
constexpr int Kc = 32;
constexpr int Lc = 64;
constexpr int Sc = Qc - Kc + 1;   // 993
constexpr int RS = 140;           // wsq_T row stride (nrow*140 mod 32: 8 banks)

// D = A*B + {c0,c0,c1,c1}
#define MMAC(d0,d1,d2,d3, a0,a1,a2,a3, b0,b1, c0,c1) \
    asm("mma.sync.aligned.m16n8k16.row.col.f32.f16.f16.f32 " \
        "{%0,%1,%2,%3}, {%4,%5,%6,%7}, {%8,%9}, {%10,%11,%12,%13};" \
        : "=f"(d0), "=f"(d1), "=f"(d2), "=f"(d3) \
        : "r"(a0), "r"(a1), "r"(a2), "r"(a3), "r"(b0), "r"(b1), \
          "f"(c0), "f"(c0), "f"(c1), "f"(c1))

// D += A*B
#define MMAB(d0,d1,d2,d3, a0,a1,a2,a3, b0,b1) \
    asm("mma.sync.aligned.m16n8k16.row.col.f32.f16.f16.f32 " \
        "{%0,%1,%2,%3}, {%4,%5,%6,%7}, {%8,%9}, {%0,%1,%2,%3};" \
        : "+f"(d0), "+f"(d1), "+f"(d2), "+f"(d3) \
        : "r"(a0), "r"(a1), "r"(a2), "r"(a3), "r"(b0), "r"(b1))

// common MMA body + ring refill for one m16 tile into set S
#define TILE_CORE(O, S, TT, WQX, WQY) do { \
    enum { I0 = (O) % 6, I1 = ((O) + 1) % 6, I2 = ((O) + 2) % 6, \
           I3 = ((O) + 3) % 6, I4 = ((O) + 4) % 6, S5 = ((O) + 5) % 6 }; \
    const int s0_ = (TT) << 4; \
    MMAC(d##S##0,d##S##1,d##S##2,d##S##3, rr[I0],rr[I1],rr[I1],rr[I2], \
         Bf[0][0][0],Bf[0][0][1], WQX, WQY); \
    MMAC(d##S##4,d##S##5,d##S##6,d##S##7, rr[I0],rr[I1],rr[I1],rr[I2], \
         Bf[1][0][0],Bf[1][0][1], WQX, WQY); \
    MMAB(d##S##0,d##S##1,d##S##2,d##S##3, rr[I2],rr[I3],rr[I3],rr[I4], \
         Bf[0][1][0],Bf[0][1][1]); \
    MMAB(d##S##4,d##S##5,d##S##6,d##S##7, rr[I2],rr[I3],rr[I3],rr[I4], \
         Bf[1][1][0],Bf[1][1][1]); \
    { const uint2 p_ = pp[s0_ + tbx + 40]; \
      rr[S5] = p_.x;  rr[I0] = p_.y; } \
} while (0)

// A-tile (even TT): uses wqA, no wq load
#define TILE_A(O, TT) TILE_CORE(O, A, TT, wqA.x, wqA.y)

// B-tile (odd TT): uses wqB, then one LDS.128 loads wq for tiles TT+1, TT+2
#define TILE_B(O, TT) do { \
    TILE_CORE(O, B, TT, wqB.x, wqB.y); \
    const float4 q4_ = *reinterpret_cast<const float4*>( \
        wsq_T + nrowRS + 2 * (TT) + 2); \
    wqA = make_float2(q4_.x, q4_.y); \
    wqB = make_float2(q4_.z, q4_.w); \
} while (0)

#define MERGE_S(S) do { \
    mn00 = fminf(mn00, d##S##0);  mn01 = fminf(mn01, d##S##1); \
    mn02 = fminf(mn02, d##S##2);  mn03 = fminf(mn03, d##S##3); \
    mn10 = fminf(mn10, d##S##4);  mn11 = fminf(mn11, d##S##5); \
    mn12 = fminf(mn12, d##S##6);  mn13 = fminf(mn13, d##S##7); \
} while (0)

static __device__ __forceinline__ uint32_t pack_f16x2(float lo, float hi) {
    uint32_t r;
    asm("cvt.rn.f16x2.f32 %0, %1, %2;" : "=r"(r) : "f"(hi), "f"(lo));
    return r;
}

__global__ __launch_bounds__(128, 8) void shapelet_hmma(
    const float* __restrict__ ts,        // [B, Q]
    const float* __restrict__ shp,       // [L, K]
    const float* __restrict__ fc_w,      // [2, L]
    const float* __restrict__ fc_b,      // [2]
    float* __restrict__ out)             // [B, 2]
{
    __shared__ __align__(16) float ts_sh[1152];     // fp32, zero-padded
    __shared__ __align__(16) uint2 pp[1120];        // {pair(i), pair(i+8)}
    __shared__ __align__(16) float wsq_T[8 * RS];   // transposed wsq
    __shared__ __align__(16) float shp_sh[Lc * 33]; // padded shapelets
    __shared__ float nh[4 * 32];                    // next-warp P heads
    __shared__ float warp_tot[4];
    __shared__ float ssq_sh[Lc];
    __shared__ float dsh[Lc];

    const int b    = blockIdx.x;
    const int tid  = threadIdx.x;
    const int w    = tid >> 5;
    const int lane = tid & 31;
    const int nrow = lane >> 2;
    const int kq   = lane & 3;

    // ---- stage ts (coalesced) + zero pad; stage shp (coalesced, padded) ----
    {
        const float4* src = reinterpret_cast<const float4*>(ts + (size_t)b * Qc);
        float4* dst = reinterpret_cast<float4*>(ts_sh);
        dst[tid]       = src[tid];
        dst[128 + tid] = src[128 + tid];
        if (tid < 32) dst[256 + tid] = make_float4(0.f, 0.f, 0.f, 0.f);
    }
    {
        const float4* gs4 = reinterpret_cast<const float4*>(shp);
        #pragma unroll
        for (int j = 0; j < 4; j++) {
            const int i4 = tid + 128 * j;           // 0..511
            const float4 v = gs4[i4];
            const int base = i4 * 4;
            float* d = &shp_sh[(base >> 5) * 33 + (base & 31)];
            d[0] = v.x; d[1] = v.y; d[2] = v.z; d[3] = v.w;
        }
    }
    __syncthreads();

    // ---- packed fp16 pair array (double-pair uint2) ----
    #pragma unroll
    for (int i = tid; i < 1120; i += 128)
        pp[i] = make_uint2(pack_f16x2(ts_sh[i],     ts_sh[i + 1]),
                           pack_f16x2(ts_sh[i + 8], ts_sh[i + 9]));

    // ---- register scan for P(s) = prefix sum of ts^2 ----
    float ex[8], e = 0.f, warp_excl;
    {
        const float4 q0 = reinterpret_cast<const float4*>(ts_sh)[tid * 2];
        const float4 q1 = reinterpret_cast<const float4*>(ts_sh)[tid * 2 + 1];
        const float sq[8] = { q0.x*q0.x, q0.y*q0.y, q0.z*q0.z, q0.w*q0.w,
                              q1.x*q1.x, q1.y*q1.y, q1.z*q1.z, q1.w*q1.w };
        #pragma unroll
        for (int k = 0; k < 8; k++) { ex[k] = e; e += sq[k]; }
        float v = e;
        #pragma unroll
        for (int off = 1; off < 32; off <<= 1) {
            const float n = __shfl_up_sync(0xffffffffu, v, off);
            if (lane >= off) v += n;
        }
        if (lane == 31) warp_tot[w] = v;
        warp_excl = v - e;
    }
    __syncthreads();   // warp_tot ready

    float pk[8], total = 0.f;
    {
        float wb = 0.f;
        #pragma unroll
        for (int j = 0; j < 4; j++) {
            total += warp_tot[j];
            if (j < w) wb += warp_tot[j];
        }
        const float tb0 = wb + warp_excl;
        #pragma unroll
        for (int k = 0; k < 8; k++) pk[k] = tb0 + ex[k];   // P(8*tid+k)
        if (lane < 4) {
            #pragma unroll
            for (int k = 0; k < 8; k++) nh[w * 32 + lane * 8 + k] = pk[k];
        }
    }

    // ---- ssq[l] exact fp32 (SMEM, conflict-free stride 33) ----
    if (tid < Lc) {
        float s = 0.f;
        #pragma unroll
        for (int k = 0; k < Kc; k++) {
            const float v = shp_sh[tid * 33 + k];
            s = fmaf(v, v, s);
        }
        ssq_sh[tid] = s;
    }

    // ---- B fragments (fp16, pre-scaled by -2) from SMEM ----
    uint32_t Bf[2][2][2];
    #pragma unroll
    for (int nt = 0; nt < 2; nt++)
        #pragma unroll
        for (int kc = 0; kc < 2; kc++)
            #pragma unroll
            for (int j = 0; j < 2; j++) {
                const int n = w * 16 + nt * 8 + nrow;
                const int k = 16 * kc + 8 * j + 2 * kq;
                Bf[nt][kc][j] = pack_f16x2(-2.0f * shp_sh[n * 33 + k],
                                           -2.0f * shp_sh[n * 33 + k + 1]);
            }
    __syncthreads();   // nh ready

    // ---- wsq[s] = P(s+32) - P(s), stored transposed (coalesced STS) ----
    {
        float p4[8];
        #pragma unroll
        for (int k = 0; k < 8; k++)
            p4[k] = __shfl_down_sync(0xffffffffu, pk[k], 4);
        if (lane >= 28 && w < 3) {
            #pragma unroll
            for (int k = 0; k < 8; k++)
                p4[k] = nh[(w + 1) * 32 + (lane - 28) * 8 + k];
        }
        #pragma unroll
        for (int k = 0; k < 8; k++) {
            const int s = tid * 8 + k;
            float wv = 1e38f;
            if (s < Sc) wv = (s == 992) ? (total - pk[k]) : (p4[k] - pk[k]);
            wsq_T[k * RS + tid] = wv;
        }
        if (tid < 64) {   // guard cols 128..135 (s in [1024,1088))
            const int s = 1024 + tid;
            wsq_T[(s & 7) * RS + (s >> 3)] = 1e38f;
        }
    }
    __syncthreads();

    // ---- main loop: 66 m16 tiles, 6-slot pair ring, pipelined merge ----
    float mn00 = 3.4e38f, mn01 = 3.4e38f, mn02 = 3.4e38f, mn03 = 3.4e38f;
    float mn10 = 3.4e38f, mn11 = 3.4e38f, mn12 = 3.4e38f, mn13 = 3.4e38f;

    const int tbx = nrow + 2 * kq;   // in [0,13]
    const int nrowRS = nrow * RS;
    uint32_t rr[6];
    {
        const uint2 u0 = pp[tbx];
        const uint2 u1 = pp[tbx + 16];
        const uint2 u2 = pp[tbx + 32];
        rr[0] = u0.x; rr[1] = u0.y;
        rr[2] = u1.x; rr[3] = u1.y;
        rr[4] = u2.x; rr[5] = 0u;
    }

    float dA0,dA1,dA2,dA3,dA4,dA5,dA6,dA7;
    float dB0,dB1,dB2,dB3,dB4,dB5,dB6,dB7;

    // wq prologue: one LDS.128 covers tiles 0 (A) and 1 (B)
    float2 wqA, wqB;
    {
        const float4 q0 = *reinterpret_cast<const float4*>(wsq_T + nrowRS);
        wqA = make_float2(q0.x, q0.y);
        wqB = make_float2(q0.z, q0.w);
    }

    #pragma unroll 1
    for (int it = 0; it < 11; it++) {
        const int t6 = it * 6;
        TILE_A(0, t6);
        TILE_B(2, t6 + 1);
        MERGE_S(A);
        TILE_A(4, t6 + 2);
        MERGE_S(B);
        TILE_B(0, t6 + 3);
        MERGE_S(A);
        TILE_A(2, t6 + 4);
        MERGE_S(B);
        TILE_B(4, t6 + 5);
        MERGE_S(A);
        MERGE_S(B);
    }

    // ---- reduce rows in-thread, then across row groups via shfl ----
    float m0 = fminf(mn00, mn02);
    float m1 = fminf(mn01, mn03);
    float m2 = fminf(mn10, mn12);
    float m3 = fminf(mn11, mn13);
    #pragma unroll
    for (int off = 4; off < 32; off <<= 1) {
        m0 = fminf(m0, __shfl_xor_sync(0xffffffffu, m0, off));
        m1 = fminf(m1, __shfl_xor_sync(0xffffffffu, m1, off));
        m2 = fminf(m2, __shfl_xor_sync(0xffffffffu, m2, off));
        m3 = fminf(m3, __shfl_xor_sync(0xffffffffu, m3, off));
    }
    if (nrow == 0) {
        const int n0 = w * 16 + 2 * kq;
        dsh[n0]     = (m0 + ssq_sh[n0])     * (1.0f / Kc);
        dsh[n0 + 1] = (m1 + ssq_sh[n0 + 1]) * (1.0f / Kc);
        dsh[n0 + 8] = (m2 + ssq_sh[n0 + 8]) * (1.0f / Kc);
        dsh[n0 + 9] = (m3 + ssq_sh[n0 + 9]) * (1.0f / Kc);
    }
    __syncthreads();

    // ---- FC epilogue ----
    if (tid < 2 * 32) {
        const int c = tid >> 5;
        const int l = tid & 31;
        float p = dsh[l] * fc_w[c * Lc + l]
                + dsh[l + 32] * fc_w[c * Lc + l + 32];
        #pragma unroll
        for (int off = 16; off > 0; off >>= 1)
            p += __shfl_down_sync(0xffffffffu, p, off);
        if (l == 0) out[b * 2 + c] = p + fc_b[c];
    }
}

extern "C" void kernel_launch(void* const* d_in, const int* in_sizes, int n_in,
                              void* d_out, int out_size)
{
    (void)in_sizes; (void)n_in; (void)out_size;
    const float* ts   = (const float*)d_in[0];
    const float* shp  = (const float*)d_in[1];
    const float* fc_w = (const float*)d_in[2];
    const float* fc_b = (const float*)d_in[3];
    float* out        = (float*)d_out;
    shapelet_hmma<<<Bc, 128>>>(ts, shp, fc_w, fc_b, out);
}